// round 1
// baseline (speedup 1.0000x reference)
#include <cuda_runtime.h>
#include <math.h>

// Problem constants (fixed by the reference)
#define B     4
#define S     8192
#define D     512
#define H     8
#define DH    64
#define M_TOT (B * S)          // 32768
#define EPSV  1e-6f

// Output layout: out [B,S,D] | k_v [B,H,DH,DH] | z [B,1,H,DH]
#define OUT_ELEMS  (M_TOT * D)                 // 16777216
#define KV_ELEMS   (B * H * DH * DH)           // 131072
#define Z_ELEMS    (B * H * DH)                // 2048
#define KV_OFF     OUT_ELEMS
#define Z_OFF      (OUT_ELEMS + KV_ELEMS)

// Scratch (static __device__ — no allocation allowed)
__device__ float g_Q[M_TOT * D];
__device__ float g_K[M_TOT * D];
__device__ float g_V[M_TOT * D];
__device__ float g_O[M_TOT * D];

#define NCHUNK 64               // 8192 / 128 rows per chunk
__device__ float g_kvp[NCHUNK * B * H * DH * DH];   // 8.4M floats
__device__ float g_zp [NCHUNK * B * H * DH];
__device__ float g_kv [B * H * DH * DH];
__device__ float g_z  [B * H * DH];

// ---------------------------------------------------------------------------
// SGEMM: C[m,n] = sum_k X[m,k] * W[n,k] + bias[n], optional elu(x)+1 epilogue.
// X: [M_TOT, 512] row-major, W: [512, 512] row-major (so this is X @ W^T).
// Tile 128x128, BK=8, 256 threads, 8x8 micro-tile per thread.
// ---------------------------------------------------------------------------
__global__ __launch_bounds__(256, 2)
void gemm512(const float* __restrict__ X, const float* __restrict__ W,
             const float* __restrict__ bias, float* __restrict__ C, int act) {
    __shared__ float As[8][128];
    __shared__ float Bs[8][128];

    const int tid      = threadIdx.x;
    const int blockRow = blockIdx.x;       // M_TOT/128 tiles
    const int blockCol = blockIdx.y;       // 4 tiles of N=512

    const float* Xb = X + (size_t)blockRow * 128 * D;
    const float* Wb = W + (size_t)blockCol * 128 * D;

    const int loadRow = tid >> 1;          // 0..127
    const int loadCol = (tid & 1) * 4;     // 0 or 4
    const int tr = (tid >> 4) * 8;         // thread micro-tile row base
    const int tc = (tid & 15) * 8;         // thread micro-tile col base

    float acc[8][8];
#pragma unroll
    for (int i = 0; i < 8; i++)
#pragma unroll
        for (int j = 0; j < 8; j++) acc[i][j] = 0.f;

    for (int kb = 0; kb < D; kb += 8) {
        float4 a = *(const float4*)(Xb + (size_t)loadRow * D + kb + loadCol);
        float4 b = *(const float4*)(Wb + (size_t)loadRow * D + kb + loadCol);
        As[loadCol + 0][loadRow] = a.x;
        As[loadCol + 1][loadRow] = a.y;
        As[loadCol + 2][loadRow] = a.z;
        As[loadCol + 3][loadRow] = a.w;
        Bs[loadCol + 0][loadRow] = b.x;
        Bs[loadCol + 1][loadRow] = b.y;
        Bs[loadCol + 2][loadRow] = b.z;
        Bs[loadCol + 3][loadRow] = b.w;
        __syncthreads();

#pragma unroll
        for (int k = 0; k < 8; k++) {
            float ra[8], rb[8];
#pragma unroll
            for (int i = 0; i < 8; i++) ra[i] = As[k][tr + i];
#pragma unroll
            for (int j = 0; j < 8; j++) rb[j] = Bs[k][tc + j];
#pragma unroll
            for (int i = 0; i < 8; i++)
#pragma unroll
                for (int j = 0; j < 8; j++) acc[i][j] = fmaf(ra[i], rb[j], acc[i][j]);
        }
        __syncthreads();
    }

    // Epilogue
    float bvals[8];
#pragma unroll
    for (int j = 0; j < 8; j++) bvals[j] = bias[blockCol * 128 + tc + j];

#pragma unroll
    for (int i = 0; i < 8; i++) {
        const size_t row = (size_t)blockRow * 128 + tr + i;
        float4 o0, o1;
        float tmp[8];
#pragma unroll
        for (int j = 0; j < 8; j++) {
            float c = acc[i][j] + bvals[j];
            if (act) c = (c > 0.f) ? (c + 1.f) : expf(c);   // elu(x)+1
            tmp[j] = c;
        }
        o0 = make_float4(tmp[0], tmp[1], tmp[2], tmp[3]);
        o1 = make_float4(tmp[4], tmp[5], tmp[6], tmp[7]);
        float* cp = C + row * D + blockCol * 128 + tc;
        *(float4*)(cp + 0) = o0;
        *(float4*)(cp + 4) = o1;
    }
}

// ---------------------------------------------------------------------------
// Stage 2: partial kv[d][m] = sum_s K[s][d]*V[s][m], z[d] = sum_s K[s][d]
// per (b,h) over a 128-row s-chunk. Deterministic two-phase reduction.
// ---------------------------------------------------------------------------
__global__ __launch_bounds__(256)
void kv_partial() {
    const int bh    = blockIdx.x;          // 0..31
    const int chunk = blockIdx.y;          // 0..NCHUNK-1
    const int b = bh >> 3, h = bh & 7;

    __shared__ float Ks[16][64];
    __shared__ float Vs[16][64];

    const int t  = threadIdx.x;
    const int m  = t & 63;
    const int dg = t >> 6;                 // 0..3 (d group of 16)

    float acc[16];
#pragma unroll
    for (int i = 0; i < 16; i++) acc[i] = 0.f;
    float zacc = 0.f;

    const int r = t >> 4;                  // load row 0..15
    const int c = (t & 15) * 4;            // load col

    for (int tile = 0; tile < 8; tile++) {
        const int s0 = chunk * 128 + tile * 16;
        const size_t base = ((size_t)(b * S + s0 + r)) * D + h * DH + c;
        *(float4*)&Ks[r][c] = *(const float4*)(g_K + base);
        *(float4*)&Vs[r][c] = *(const float4*)(g_V + base);
        __syncthreads();

#pragma unroll
        for (int rr = 0; rr < 16; rr++) {
            const float v = Vs[rr][m];
#pragma unroll
            for (int i = 0; i < 16; i++)
                acc[i] = fmaf(Ks[rr][dg * 16 + i], v, acc[i]);
        }
        if (t < 64) {
#pragma unroll
            for (int rr = 0; rr < 16; rr++) zacc += Ks[rr][t];
        }
        __syncthreads();
    }

    float* kvo = g_kvp + ((size_t)chunk * 32 + bh) * (DH * DH);
#pragma unroll
    for (int i = 0; i < 16; i++)
        kvo[(dg * 16 + i) * DH + m] = acc[i];
    if (t < 64)
        g_zp[((size_t)chunk * 32 + bh) * DH + t] = zacc;
}

// Reduce partials; also write k_v and z output tails (if present).
__global__ __launch_bounds__(256)
void kv_reduce(float* __restrict__ out_kv, float* __restrict__ out_z) {
    const int bh = blockIdx.x;
    const int t  = threadIdx.x;
    for (int idx = t; idx < DH * DH; idx += 256) {
        float sum = 0.f;
        for (int c = 0; c < NCHUNK; c++)
            sum += g_kvp[((size_t)c * 32 + bh) * (DH * DH) + idx];
        g_kv[bh * DH * DH + idx] = sum;
        if (out_kv) out_kv[bh * DH * DH + idx] = sum;
    }
    if (t < DH) {
        float sum = 0.f;
        for (int c = 0; c < NCHUNK; c++)
            sum += g_zp[((size_t)c * 32 + bh) * DH + t];
        g_z[bh * DH + t] = sum;
        if (out_z) out_z[bh * DH + t] = sum;
    }
}

// ---------------------------------------------------------------------------
// Stage 3: O[s, h*64+m] = (sum_d Q[s][d]*kv[d][m]) / (sum_d Q[s][d]*z[d] + eps)
// Block: one (b,h), 64 s-rows.
// ---------------------------------------------------------------------------
__global__ __launch_bounds__(256)
void attn_out() {
    const int bh = blockIdx.x;             // 0..31
    const int sb = blockIdx.y;             // 0..127
    const int b = bh >> 3, h = bh & 7;

    __shared__ float kvs[64][64];
    __shared__ float Qs[64][64];
    __shared__ float zs[64];
    __shared__ float dens[64];

    const int t = threadIdx.x;
    for (int idx = t; idx < DH * DH; idx += 256)
        kvs[idx >> 6][idx & 63] = g_kv[bh * DH * DH + idx];
    if (t < 64) zs[t] = g_z[bh * DH + t];

    const int s0 = sb * 64;
    for (int idx = t; idx < 64 * 64; idx += 256)
        Qs[idx >> 6][idx & 63] =
            g_Q[((size_t)(b * S + s0 + (idx >> 6))) * D + h * DH + (idx & 63)];
    __syncthreads();

    if (t < 64) {
        float den = 0.f;
#pragma unroll
        for (int k = 0; k < 64; k++) den = fmaf(Qs[t][k], zs[k], den);
        dens[t] = den + EPSV;
    }
    __syncthreads();

    const int m  = t & 63;
    const int rg = t >> 6;
#pragma unroll
    for (int i = 0; i < 16; i++) {
        const int r = rg * 16 + i;
        float acc = 0.f;
#pragma unroll
        for (int d = 0; d < 64; d++) acc = fmaf(Qs[r][d], kvs[d][m], acc);
        g_O[((size_t)(b * S + s0 + r)) * D + h * DH + m] = acc / dens[r];
    }
}

// ---------------------------------------------------------------------------
extern "C" void kernel_launch(void* const* d_in, const int* in_sizes, int n_in,
                              void* d_out, int out_size) {
    const float* q  = (const float*)d_in[0];
    const float* k  = (const float*)d_in[1];
    const float* v  = (const float*)d_in[2];
    const float* Wq = (const float*)d_in[3];
    const float* bq = (const float*)d_in[4];
    const float* Wk = (const float*)d_in[5];
    const float* bk = (const float*)d_in[6];
    const float* Wv = (const float*)d_in[7];
    const float* bv = (const float*)d_in[8];
    const float* Wo = (const float*)d_in[9];
    const float* bo = (const float*)d_in[10];
    float* out = (float*)d_out;

    float* gQ; cudaGetSymbolAddress((void**)&gQ, g_Q);
    float* gK; cudaGetSymbolAddress((void**)&gK, g_K);
    float* gV; cudaGetSymbolAddress((void**)&gV, g_V);
    float* gO; cudaGetSymbolAddress((void**)&gO, g_O);

    dim3 gg(M_TOT / 128, D / 128);

    // Stage 1: projections (+ elu+1 for Q,K)
    gemm512<<<gg, 256>>>(q, Wq, bq, gQ, 1);
    gemm512<<<gg, 256>>>(k, Wk, bk, gK, 1);
    gemm512<<<gg, 256>>>(v, Wv, bv, gV, 0);

    // Stage 2: kv summary + z (deterministic two-phase)
    kv_partial<<<dim3(B * H, NCHUNK), 256>>>();
    float* out_kv = (out_size >= Z_OFF + Z_ELEMS) ? (out + KV_OFF) : nullptr;
    float* out_z  = (out_size >= Z_OFF + Z_ELEMS) ? (out + Z_OFF)  : nullptr;
    kv_reduce<<<B * H, 256>>>(out_kv, out_z);

    // Stage 3: attention recall + normalization
    attn_out<<<dim3(B * H, S / 64), 256>>>();

    // Stage 4: output projection
    gemm512<<<gg, 256>>>(gO, Wo, bo, out, 0);
}

// round 13
// speedup vs baseline: 2.1170x; 2.1170x over previous
#include <cuda_runtime.h>
#include <cuda_bf16.h>
#include <math.h>
#include <stdint.h>

// Problem constants
#define B     4
#define S     8192
#define D     512
#define H     8
#define DH    64
#define M_TOT (B * S)          // 32768
#define EPSV  1e-6f

// Output layout: out [B,S,D] | k_v [B,H,DH,DH] | z [B,1,H,DH]
#define OUT_ELEMS  (M_TOT * D)
#define KV_ELEMS   (B * H * DH * DH)
#define Z_ELEMS    (B * H * DH)
#define KV_OFF     OUT_ELEMS
#define Z_OFF      (OUT_ELEMS + KV_ELEMS)

// ---------------- scratch (static __device__, no allocation) ----------------
__device__ __align__(256) float g_Q[M_TOT * D];
__device__ __align__(256) float g_K[M_TOT * D];
__device__ __align__(256) float g_V[M_TOT * D];
__device__ __align__(256) float g_O[M_TOT * D];

__device__ __align__(256) __nv_bfloat16 g_Xhi[M_TOT * D];
__device__ __align__(256) __nv_bfloat16 g_Xlo[M_TOT * D];
__device__ __align__(256) __nv_bfloat16 g_Whi[D * D];
__device__ __align__(256) __nv_bfloat16 g_Wlo[D * D];

#define NCHUNK 64
__device__ float g_kvp[NCHUNK * B * H * DH * DH];
__device__ float g_zp [NCHUNK * B * H * DH];
__device__ float g_kv [B * H * DH * DH];
__device__ float g_z  [B * H * DH];

// ---------------------------- PTX helpers -----------------------------------
__device__ __forceinline__ uint32_t smem_u32(const void* p) {
    uint32_t a;
    asm("{ .reg .u64 t; cvta.to.shared.u64 t, %1; cvt.u32.u64 %0, t; }"
        : "=r"(a) : "l"(p));
    return a;
}

__device__ __forceinline__ void cp_async16(uint32_t dst, const void* src) {
    asm volatile("cp.async.cg.shared.global [%0], [%1], 16;"
                 :: "r"(dst), "l"(src));
}
__device__ __forceinline__ void cp_commit() {
    asm volatile("cp.async.commit_group;");
}
template <int N>
__device__ __forceinline__ void cp_wait() {
    asm volatile("cp.async.wait_group %0;" :: "n"(N));
}

__device__ __forceinline__ void ldsm_x4(uint32_t* r, uint32_t addr) {
    asm volatile("ldmatrix.sync.aligned.m8n8.x4.shared.b16 {%0,%1,%2,%3}, [%4];"
                 : "=r"(r[0]), "=r"(r[1]), "=r"(r[2]), "=r"(r[3]) : "r"(addr));
}

__device__ __forceinline__ void mma_bf16(float* c, const uint32_t* a,
                                         const uint32_t* b) {
    asm volatile(
        "mma.sync.aligned.m16n8k16.row.col.f32.bf16.bf16.f32 "
        "{%0,%1,%2,%3}, {%4,%5,%6,%7}, {%8,%9}, {%0,%1,%2,%3};"
        : "+f"(c[0]), "+f"(c[1]), "+f"(c[2]), "+f"(c[3])
        : "r"(a[0]), "r"(a[1]), "r"(a[2]), "r"(a[3]), "r"(b[0]), "r"(b[1]));
}

// ---------------------------------------------------------------------------
// fp32 -> (bf16 hi, bf16 lo) split.  x ~= hi + lo with residual ~2^-18 |x|.
// ---------------------------------------------------------------------------
__global__ __launch_bounds__(256)
void split_bf16(const float* __restrict__ x, __nv_bfloat16* __restrict__ hi,
                __nv_bfloat16* __restrict__ lo, int n4) {
    int i = blockIdx.x * 256 + threadIdx.x;
    if (i >= n4) return;
    float4 v = ((const float4*)x)[i];
    __nv_bfloat16 h0 = __float2bfloat16_rn(v.x);
    __nv_bfloat16 h1 = __float2bfloat16_rn(v.y);
    __nv_bfloat16 h2 = __float2bfloat16_rn(v.z);
    __nv_bfloat16 h3 = __float2bfloat16_rn(v.w);
    __nv_bfloat16 l0 = __float2bfloat16_rn(v.x - __bfloat162float(h0));
    __nv_bfloat16 l1 = __float2bfloat16_rn(v.y - __bfloat162float(h1));
    __nv_bfloat16 l2 = __float2bfloat16_rn(v.z - __bfloat162float(h2));
    __nv_bfloat16 l3 = __float2bfloat16_rn(v.w - __bfloat162float(h3));
    __nv_bfloat162* hp = (__nv_bfloat162*)(hi + (size_t)i * 4);
    __nv_bfloat162* lp = (__nv_bfloat162*)(lo + (size_t)i * 4);
    hp[0] = __nv_bfloat162(h0, h1);
    hp[1] = __nv_bfloat162(h2, h3);
    lp[0] = __nv_bfloat162(l0, l1);
    lp[1] = __nv_bfloat162(l2, l3);
}

// ---------------------------------------------------------------------------
// HMMA GEMM: C[128x128 tile] = X[M x 512] @ W^T (+bias, opt elu+1)
// bf16 2-term split, 3 passes: hi*hi + hi*lo + lo*hi, fp32 accumulate.
// 256 threads = 8 warps, warp tile 32x64 (2 m-frags x 8 n-frags), BK=32,
// cp.async double buffering.
// ---------------------------------------------------------------------------
#define BK     32
#define NCK    (D / BK)          // 16
#define TS     40                // smem row stride in bf16 (padded from 32)
#define TILE_B (128 * TS * 2)    // 10240 bytes per tile
#define BUF_B  (4 * TILE_B)      // Ahi, Alo, Bhi, Blo
#define SMEM_SZ (2 * BUF_B)      // 81920 bytes

__global__ __launch_bounds__(256)
void gemm_mma(const __nv_bfloat16* __restrict__ Xhi,
              const __nv_bfloat16* __restrict__ Xlo,
              const __nv_bfloat16* __restrict__ Whi,
              const __nv_bfloat16* __restrict__ Wlo,
              const float* __restrict__ bias, float* __restrict__ C, int act) {
    extern __shared__ char smem[];
    const uint32_t sb = smem_u32(smem);

    const int tid  = threadIdx.x;
    const int wid  = tid >> 5;
    const int lane = tid & 31;
    const int bm   = blockIdx.x;           // 256 m-tiles
    const int bn   = blockIdx.y;           // 4 n-tiles
    const int wr   = wid >> 1;             // warp row 0..3  (32 rows each)
    const int wc   = wid & 1;              // warp col 0..1  (64 cols each)

    const __nv_bfloat16* Ah = Xhi + (size_t)bm * 128 * D;
    const __nv_bfloat16* Al = Xlo + (size_t)bm * 128 * D;
    const __nv_bfloat16* Bh = Whi + (size_t)bn * 128 * D;
    const __nv_bfloat16* Bl = Wlo + (size_t)bn * 128 * D;

    // ---- async fill of one k-chunk into buffer `buf` ----
    auto issue = [&](int ck, int buf) {
        const int koff = ck * BK;
        const uint32_t base = sb + buf * BUF_B;
#pragma unroll
        for (int i = tid; i < 512; i += 256) {     // 128 rows x 4 segs of 16B
            const int row = i >> 2, seg = i & 3;
            const uint32_t d = (uint32_t)(row * (TS * 2) + seg * 16);
            const size_t  s = (size_t)row * D + koff + seg * 8;
            cp_async16(base + 0 * TILE_B + d, Ah + s);
            cp_async16(base + 1 * TILE_B + d, Al + s);
            cp_async16(base + 2 * TILE_B + d, Bh + s);
            cp_async16(base + 3 * TILE_B + d, Bl + s);
        }
        cp_commit();
    };

    float acc[2][8][4];
#pragma unroll
    for (int m = 0; m < 2; m++)
#pragma unroll
        for (int n = 0; n < 8; n++)
#pragma unroll
            for (int j = 0; j < 4; j++) acc[m][n][j] = 0.f;

    issue(0, 0);

    for (int ck = 0; ck < NCK; ck++) {
        const int buf = ck & 1;
        if (ck + 1 < NCK) { issue(ck + 1, buf ^ 1); cp_wait<1>(); }
        else              { cp_wait<0>(); }
        __syncthreads();

        const uint32_t ahi = sb + buf * BUF_B + 0 * TILE_B;
        const uint32_t alo = sb + buf * BUF_B + 1 * TILE_B;
        const uint32_t bhi = sb + buf * BUF_B + 2 * TILE_B;
        const uint32_t blo = sb + buf * BUF_B + 3 * TILE_B;

#pragma unroll
        for (int ks = 0; ks < 2; ks++) {           // two k16 steps per chunk
            // A fragments: lanes 0-15 rows, lanes 16-31 k+8 half
            const int ar = lane & 15, ac = (lane >> 4) * 8;
            uint32_t a_h[2][4], a_l[2][4];
#pragma unroll
            for (int mt = 0; mt < 2; mt++) {
                const uint32_t off =
                    (uint32_t)((wr * 32 + mt * 16 + ar) * TS + ks * 16 + ac) * 2;
                ldsm_x4(a_h[mt], ahi + off);
                ldsm_x4(a_l[mt], alo + off);
            }
            // B fragments: x4 covers 16 n x 16 k
            const int bp = lane & 7, bk8 = ((lane >> 3) & 1) * 8,
                      bn8 = ((lane >> 4) & 1) * 8;
            uint32_t b_h[16], b_l[16];
#pragma unroll
            for (int nt4 = 0; nt4 < 4; nt4++) {
                const int nrow = wc * 64 + nt4 * 16 + bp + bn8;
                const uint32_t off = (uint32_t)(nrow * TS + ks * 16 + bk8) * 2;
                ldsm_x4(&b_h[nt4 * 4], bhi + off);
                ldsm_x4(&b_l[nt4 * 4], blo + off);
            }
            // 3 passes: hi*hi, hi*lo, lo*hi
#pragma unroll
            for (int mt = 0; mt < 2; mt++)
#pragma unroll
                for (int nt = 0; nt < 8; nt++) {
                    const int bi = (nt >> 1) * 4 + (nt & 1) * 2;
                    mma_bf16(acc[mt][nt], a_h[mt], &b_h[bi]);
                    mma_bf16(acc[mt][nt], a_h[mt], &b_l[bi]);
                    mma_bf16(acc[mt][nt], a_l[mt], &b_h[bi]);
                }
        }
        __syncthreads();
    }

    // ---- epilogue: bias + optional elu(x)+1, direct global stores ----
    const int r0b = bm * 128 + wr * 32 + (lane >> 2);
    const int c0b = bn * 128 + wc * 64 + (lane & 3) * 2;
#pragma unroll
    for (int mt = 0; mt < 2; mt++) {
#pragma unroll
        for (int nt = 0; nt < 8; nt++) {
            const int col = c0b + nt * 8;
            const float b0 = bias[col], b1 = bias[col + 1];
            float v[4];
            v[0] = acc[mt][nt][0] + b0;
            v[1] = acc[mt][nt][1] + b1;
            v[2] = acc[mt][nt][2] + b0;
            v[3] = acc[mt][nt][3] + b1;
            if (act) {
#pragma unroll
                for (int j = 0; j < 4; j++)
                    v[j] = (v[j] > 0.f) ? (v[j] + 1.f) : expf(v[j]);
            }
            const size_t r0 = (size_t)(r0b + mt * 16) * D + col;
            const size_t r1 = r0 + 8 * D;
            *(float2*)(C + r0) = make_float2(v[0], v[1]);
            *(float2*)(C + r1) = make_float2(v[2], v[3]);
        }
    }
}

// ---------------------------------------------------------------------------
// Stage 2: partial kv / z per (b,h) over 128-row s-chunks
// ---------------------------------------------------------------------------
__global__ __launch_bounds__(256)
void kv_partial() {
    const int bh    = blockIdx.x;
    const int chunk = blockIdx.y;
    const int b = bh >> 3, h = bh & 7;

    __shared__ float Ks[16][64];
    __shared__ float Vs[16][64];

    const int t  = threadIdx.x;
    const int m  = t & 63;
    const int dg = t >> 6;

    float acc[16];
#pragma unroll
    for (int i = 0; i < 16; i++) acc[i] = 0.f;
    float zacc = 0.f;

    const int r = t >> 4;
    const int c = (t & 15) * 4;

    for (int tile = 0; tile < 8; tile++) {
        const int s0 = chunk * 128 + tile * 16;
        const size_t base = ((size_t)(b * S + s0 + r)) * D + h * DH + c;
        *(float4*)&Ks[r][c] = *(const float4*)(g_K + base);
        *(float4*)&Vs[r][c] = *(const float4*)(g_V + base);
        __syncthreads();

#pragma unroll
        for (int rr = 0; rr < 16; rr++) {
            const float v = Vs[rr][m];
#pragma unroll
            for (int i = 0; i < 16; i++)
                acc[i] = fmaf(Ks[rr][dg * 16 + i], v, acc[i]);
        }
        if (t < 64) {
#pragma unroll
            for (int rr = 0; rr < 16; rr++) zacc += Ks[rr][t];
        }
        __syncthreads();
    }

    float* kvo = g_kvp + ((size_t)chunk * 32 + bh) * (DH * DH);
#pragma unroll
    for (int i = 0; i < 16; i++)
        kvo[(dg * 16 + i) * DH + m] = acc[i];
    if (t < 64)
        g_zp[((size_t)chunk * 32 + bh) * DH + t] = zacc;
}

__global__ __launch_bounds__(256)
void kv_reduce(float* __restrict__ out_kv, float* __restrict__ out_z) {
    const int bh = blockIdx.x;
    const int t  = threadIdx.x;
    for (int idx = t; idx < DH * DH; idx += 256) {
        float sum = 0.f;
        for (int c = 0; c < NCHUNK; c++)
            sum += g_kvp[((size_t)c * 32 + bh) * (DH * DH) + idx];
        g_kv[bh * DH * DH + idx] = sum;
        if (out_kv) out_kv[bh * DH * DH + idx] = sum;
    }
    if (t < DH) {
        float sum = 0.f;
        for (int c = 0; c < NCHUNK; c++)
            sum += g_zp[((size_t)c * 32 + bh) * DH + t];
        g_z[bh * DH + t] = sum;
        if (out_z) out_z[bh * DH + t] = sum;
    }
}

// ---------------------------------------------------------------------------
// Stage 3: recall + normalize
// ---------------------------------------------------------------------------
__global__ __launch_bounds__(256)
void attn_out() {
    const int bh = blockIdx.x;
    const int sb = blockIdx.y;
    const int b = bh >> 3, h = bh & 7;

    __shared__ float kvs[64][64];
    __shared__ float Qs[64][64];
    __shared__ float zs[64];
    __shared__ float dens[64];

    const int t = threadIdx.x;
    for (int idx = t; idx < DH * DH; idx += 256)
        kvs[idx >> 6][idx & 63] = g_kv[bh * DH * DH + idx];
    if (t < 64) zs[t] = g_z[bh * DH + t];

    const int s0 = sb * 64;
    for (int idx = t; idx < 64 * 64; idx += 256)
        Qs[idx >> 6][idx & 63] =
            g_Q[((size_t)(b * S + s0 + (idx >> 6))) * D + h * DH + (idx & 63)];
    __syncthreads();

    if (t < 64) {
        float den = 0.f;
#pragma unroll
        for (int k = 0; k < 64; k++) den = fmaf(Qs[t][k], zs[k], den);
        dens[t] = den + EPSV;
    }
    __syncthreads();

    const int m  = t & 63;
    const int rg = t >> 6;
#pragma unroll
    for (int i = 0; i < 16; i++) {
        const int r = rg * 16 + i;
        float acc = 0.f;
#pragma unroll
        for (int d = 0; d < 64; d++) acc = fmaf(Qs[r][d], kvs[d][m], acc);
        g_O[((size_t)(b * S + s0 + r)) * D + h * DH + m] = acc / dens[r];
    }
}

// ---------------------------------------------------------------------------
extern "C" void kernel_launch(void* const* d_in, const int* in_sizes, int n_in,
                              void* d_out, int out_size) {
    const float* q  = (const float*)d_in[0];
    const float* k  = (const float*)d_in[1];
    const float* v  = (const float*)d_in[2];
    const float* Wq = (const float*)d_in[3];
    const float* bq = (const float*)d_in[4];
    const float* Wk = (const float*)d_in[5];
    const float* bk = (const float*)d_in[6];
    const float* Wv = (const float*)d_in[7];
    const float* bv = (const float*)d_in[8];
    const float* Wo = (const float*)d_in[9];
    const float* bo = (const float*)d_in[10];
    float* out = (float*)d_out;

    float* gQ; cudaGetSymbolAddress((void**)&gQ, g_Q);
    float* gK; cudaGetSymbolAddress((void**)&gK, g_K);
    float* gV; cudaGetSymbolAddress((void**)&gV, g_V);
    float* gO; cudaGetSymbolAddress((void**)&gO, g_O);
    __nv_bfloat16* xh; cudaGetSymbolAddress((void**)&xh, g_Xhi);
    __nv_bfloat16* xl; cudaGetSymbolAddress((void**)&xl, g_Xlo);
    __nv_bfloat16* wh; cudaGetSymbolAddress((void**)&wh, g_Whi);
    __nv_bfloat16* wl; cudaGetSymbolAddress((void**)&wl, g_Wlo);

    cudaFuncSetAttribute(gemm_mma, cudaFuncAttributeMaxDynamicSharedMemorySize,
                         SMEM_SZ);

    const int NX4 = M_TOT * D / 4;
    const int NW4 = D * D / 4;
    const dim3 gg(M_TOT / 128, D / 128);

    // Q projection
    split_bf16<<<(NX4 + 255) / 256, 256>>>(q, xh, xl, NX4);
    split_bf16<<<(NW4 + 255) / 256, 256>>>(Wq, wh, wl, NW4);
    gemm_mma<<<gg, 256, SMEM_SZ>>>(xh, xl, wh, wl, bq, gQ, 1);
    // K projection
    split_bf16<<<(NX4 + 255) / 256, 256>>>(k, xh, xl, NX4);
    split_bf16<<<(NW4 + 255) / 256, 256>>>(Wk, wh, wl, NW4);
    gemm_mma<<<gg, 256, SMEM_SZ>>>(xh, xl, wh, wl, bk, gK, 1);
    // V projection
    split_bf16<<<(NX4 + 255) / 256, 256>>>(v, xh, xl, NX4);
    split_bf16<<<(NW4 + 255) / 256, 256>>>(Wv, wh, wl, NW4);
    gemm_mma<<<gg, 256, SMEM_SZ>>>(xh, xl, wh, wl, bv, gV, 0);

    // kv summary + z
    kv_partial<<<dim3(B * H, NCHUNK), 256>>>();
    float* out_kv = (out_size >= Z_OFF + Z_ELEMS) ? (out + KV_OFF) : nullptr;
    float* out_z  = (out_size >= Z_OFF + Z_ELEMS) ? (out + Z_OFF)  : nullptr;
    kv_reduce<<<B * H, 256>>>(out_kv, out_z);

    // recall + normalize
    attn_out<<<dim3(B * H, S / 64), 256>>>();

    // output projection
    split_bf16<<<(NX4 + 255) / 256, 256>>>(gO, xh, xl, NX4);
    split_bf16<<<(NW4 + 255) / 256, 256>>>(Wo, wh, wl, NW4);
    gemm_mma<<<gg, 256, SMEM_SZ>>>(xh, xl, wh, wl, bo, out, 0);
}

// round 15
// speedup vs baseline: 2.3074x; 1.0900x over previous
#include <cuda_runtime.h>
#include <cuda_bf16.h>
#include <math.h>
#include <stdint.h>

// Problem constants
#define B     4
#define S     8192
#define D     512
#define H     8
#define DH    64
#define M_TOT (B * S)          // 32768
#define EPSV  1e-6f

// Output layout: out [B,S,D] | k_v [B,H,DH,DH] | z [B,1,H,DH]
#define OUT_ELEMS  (M_TOT * D)
#define KV_ELEMS   (B * H * DH * DH)
#define Z_ELEMS    (B * H * DH)
#define KV_OFF     OUT_ELEMS
#define Z_OFF      (OUT_ELEMS + KV_ELEMS)

// ---------------- scratch (static __device__, no allocation) ----------------
__device__ __align__(256) float g_Q[M_TOT * D];
__device__ __align__(256) float g_K[M_TOT * D];
__device__ __align__(256) float g_V[M_TOT * D];
__device__ __align__(256) float g_O[M_TOT * D];

__device__ __align__(256) __nv_bfloat16 g_Whi[D * D];
__device__ __align__(256) __nv_bfloat16 g_Wlo[D * D];

#define NCHUNK 64
__device__ float g_kvp[NCHUNK * B * H * DH * DH];
__device__ float g_zp [NCHUNK * B * H * DH];
__device__ float g_kv [B * H * DH * DH];
__device__ float g_z  [B * H * DH];

// ---------------------------- PTX helpers -----------------------------------
__device__ __forceinline__ uint32_t smem_u32(const void* p) {
    uint32_t a;
    asm("{ .reg .u64 t; cvta.to.shared.u64 t, %1; cvt.u32.u64 %0, t; }"
        : "=r"(a) : "l"(p));
    return a;
}

__device__ __forceinline__ void cp_async16(uint32_t dst, const void* src) {
    asm volatile("cp.async.cg.shared.global [%0], [%1], 16;"
                 :: "r"(dst), "l"(src));
}
__device__ __forceinline__ void cp_commit() {
    asm volatile("cp.async.commit_group;");
}
template <int N>
__device__ __forceinline__ void cp_wait() {
    asm volatile("cp.async.wait_group %0;" :: "n"(N));
}

__device__ __forceinline__ void ldsm_x4(uint32_t* r, uint32_t addr) {
    asm volatile("ldmatrix.sync.aligned.m8n8.x4.shared.b16 {%0,%1,%2,%3}, [%4];"
                 : "=r"(r[0]), "=r"(r[1]), "=r"(r[2]), "=r"(r[3]) : "r"(addr));
}

__device__ __forceinline__ void mma_bf16(float* c, const uint32_t* a,
                                         const uint32_t* b) {
    asm volatile(
        "mma.sync.aligned.m16n8k16.row.col.f32.bf16.bf16.f32 "
        "{%0,%1,%2,%3}, {%4,%5,%6,%7}, {%8,%9}, {%0,%1,%2,%3};"
        : "+f"(c[0]), "+f"(c[1]), "+f"(c[2]), "+f"(c[3])
        : "r"(a[0]), "r"(a[1]), "r"(a[2]), "r"(a[3]), "r"(b[0]), "r"(b[1]));
}

__device__ __forceinline__ uint32_t pack_bf2(__nv_bfloat16 a, __nv_bfloat16 b) {
    __nv_bfloat162 t(a, b);
    return *(uint32_t*)&t;
}

// ---------------------------------------------------------------------------
// fp32 -> (bf16 hi, bf16 lo) split for the weight matrices (tiny, kept).
// ---------------------------------------------------------------------------
__global__ __launch_bounds__(256)
void split_bf16(const float* __restrict__ x, __nv_bfloat16* __restrict__ hi,
                __nv_bfloat16* __restrict__ lo, int n4) {
    int i = blockIdx.x * 256 + threadIdx.x;
    if (i >= n4) return;
    float4 v = ((const float4*)x)[i];
    __nv_bfloat16 h0 = __float2bfloat16_rn(v.x);
    __nv_bfloat16 h1 = __float2bfloat16_rn(v.y);
    __nv_bfloat16 h2 = __float2bfloat16_rn(v.z);
    __nv_bfloat16 h3 = __float2bfloat16_rn(v.w);
    __nv_bfloat16 l0 = __float2bfloat16_rn(v.x - __bfloat162float(h0));
    __nv_bfloat16 l1 = __float2bfloat16_rn(v.y - __bfloat162float(h1));
    __nv_bfloat16 l2 = __float2bfloat16_rn(v.z - __bfloat162float(h2));
    __nv_bfloat16 l3 = __float2bfloat16_rn(v.w - __bfloat162float(h3));
    __nv_bfloat162* hp = (__nv_bfloat162*)(hi + (size_t)i * 4);
    __nv_bfloat162* lp = (__nv_bfloat162*)(lo + (size_t)i * 4);
    hp[0] = __nv_bfloat162(h0, h1);
    hp[1] = __nv_bfloat162(h2, h3);
    lp[0] = __nv_bfloat162(l0, l1);
    lp[1] = __nv_bfloat162(l2, l3);
}

// ---------------------------------------------------------------------------
// HMMA GEMM with fused fp32->bf16 hi/lo split on the A (X) path.
// C[128x128 tile] = X[M x 512] @ W^T (+bias, opt elu+1)
// 3 MMA passes: hi*hi + hi*lo + lo*hi, fp32 accumulate.
// 256 threads = 8 warps, warp tile 32x64 (2 m-frags x 8 n-frags), BK=32,
// cp.async double buffering for B; register-staged LDG+convert for A.
// ---------------------------------------------------------------------------
#define BK     32
#define NCK    (D / BK)          // 16
#define TS     40                // smem row stride in bf16 (padded from 32)
#define TILE_B (128 * TS * 2)    // 10240 bytes per tile
#define BUF_B  (4 * TILE_B)      // Ahi, Alo, Bhi, Blo
#define SMEM_SZ (2 * BUF_B)      // 81920 bytes

__global__ __launch_bounds__(256, 2)
void gemm_mma_f(const float* __restrict__ Xf,
                const __nv_bfloat16* __restrict__ Whi,
                const __nv_bfloat16* __restrict__ Wlo,
                const float* __restrict__ bias, float* __restrict__ C, int act) {
    extern __shared__ char smem[];
    const uint32_t sb = smem_u32(smem);

    const int tid  = threadIdx.x;
    const int wid  = tid >> 5;
    const int lane = tid & 31;
    const int bm   = blockIdx.x;           // 256 m-tiles
    const int bn   = blockIdx.y;           // 4 n-tiles
    const int wr   = wid >> 1;             // warp row 0..3  (32 rows each)
    const int wc   = wid & 1;              // warp col 0..1  (64 cols each)

    const float* Af = Xf + (size_t)bm * 128 * D;
    const __nv_bfloat16* Bh = Whi + (size_t)bn * 128 * D;
    const __nv_bfloat16* Bl = Wlo + (size_t)bn * 128 * D;

    // ---- B tiles: async fill of one k-chunk into buffer `buf` ----
    auto issueB = [&](int ck, int buf) {
        const int koff = ck * BK;
        const uint32_t base = sb + buf * BUF_B;
#pragma unroll
        for (int i = tid; i < 512; i += 256) {     // 128 rows x 4 segs of 16B
            const int row = i >> 2, seg = i & 3;
            const uint32_t d = (uint32_t)(row * (TS * 2) + seg * 16);
            const size_t  s = (size_t)row * D + koff + seg * 8;
            cp_async16(base + 2 * TILE_B + d, Bh + s);
            cp_async16(base + 3 * TILE_B + d, Bl + s);
        }
        cp_commit();
    };

    // ---- A tile: fp32 LDG into registers ----
    float4 xr[4];
    auto loadX = [&](int ck) {
#pragma unroll
        for (int j = 0; j < 4; j++) {
            const int i = tid + j * 256;           // 1024 float4 per tile
            const int row = i >> 3, seg = i & 7;   // 8 float4 per row (32 cols)
            xr[j] = *(const float4*)(Af + (size_t)row * D + ck * BK + seg * 4);
        }
    };
    // ---- A tile: convert + STS hi/lo into buffer `buf` ----
    auto stsA = [&](int buf) {
#pragma unroll
        for (int j = 0; j < 4; j++) {
            const int i = tid + j * 256;
            const int row = i >> 3, seg = i & 7;
            const float4 v = xr[j];
            const __nv_bfloat16 h0 = __float2bfloat16_rn(v.x);
            const __nv_bfloat16 h1 = __float2bfloat16_rn(v.y);
            const __nv_bfloat16 h2 = __float2bfloat16_rn(v.z);
            const __nv_bfloat16 h3 = __float2bfloat16_rn(v.w);
            const __nv_bfloat16 l0 = __float2bfloat16_rn(v.x - __bfloat162float(h0));
            const __nv_bfloat16 l1 = __float2bfloat16_rn(v.y - __bfloat162float(h1));
            const __nv_bfloat16 l2 = __float2bfloat16_rn(v.z - __bfloat162float(h2));
            const __nv_bfloat16 l3 = __float2bfloat16_rn(v.w - __bfloat162float(h3));
            const uint32_t off = (uint32_t)(row * TS + seg * 4) * 2;  // bytes
            *(uint2*)(smem + buf * BUF_B + 0 * TILE_B + off) =
                make_uint2(pack_bf2(h0, h1), pack_bf2(h2, h3));
            *(uint2*)(smem + buf * BUF_B + 1 * TILE_B + off) =
                make_uint2(pack_bf2(l0, l1), pack_bf2(l2, l3));
        }
    };

    float acc[2][8][4];
#pragma unroll
    for (int m = 0; m < 2; m++)
#pragma unroll
        for (int n = 0; n < 8; n++)
#pragma unroll
            for (int j = 0; j < 4; j++) acc[m][n][j] = 0.f;

    // prologue: A(0) + B(0) into buf 0
    loadX(0);
    issueB(0, 0);
    stsA(0);

    for (int ck = 0; ck < NCK; ck++) {
        const int buf = ck & 1;
        if (ck + 1 < NCK) { loadX(ck + 1); issueB(ck + 1, buf ^ 1); cp_wait<1>(); }
        else              { cp_wait<0>(); }
        __syncthreads();   // A(ck) stored, B(ck) arrived

        const uint32_t ahi = sb + buf * BUF_B + 0 * TILE_B;
        const uint32_t alo = sb + buf * BUF_B + 1 * TILE_B;
        const uint32_t bhi = sb + buf * BUF_B + 2 * TILE_B;
        const uint32_t blo = sb + buf * BUF_B + 3 * TILE_B;

#pragma unroll
        for (int ks = 0; ks < 2; ks++) {           // two k16 steps per chunk
            // A fragments: lanes 0-15 rows, lanes 16-31 k+8 half
            const int ar = lane & 15, ac = (lane >> 4) * 8;
            uint32_t a_h[2][4], a_l[2][4];
#pragma unroll
            for (int mt = 0; mt < 2; mt++) {
                const uint32_t off =
                    (uint32_t)((wr * 32 + mt * 16 + ar) * TS + ks * 16 + ac) * 2;
                ldsm_x4(a_h[mt], ahi + off);
                ldsm_x4(a_l[mt], alo + off);
            }
            // B fragments: x4 covers 16 n x 16 k
            const int bp = lane & 7, bk8 = ((lane >> 3) & 1) * 8,
                      bn8 = ((lane >> 4) & 1) * 8;
            uint32_t b_h[16], b_l[16];
#pragma unroll
            for (int nt4 = 0; nt4 < 4; nt4++) {
                const int nrow = wc * 64 + nt4 * 16 + bp + bn8;
                const uint32_t off = (uint32_t)(nrow * TS + ks * 16 + bk8) * 2;
                ldsm_x4(&b_h[nt4 * 4], bhi + off);
                ldsm_x4(&b_l[nt4 * 4], blo + off);
            }
            // 3 passes: hi*hi, hi*lo, lo*hi
#pragma unroll
            for (int mt = 0; mt < 2; mt++)
#pragma unroll
                for (int nt = 0; nt < 8; nt++) {
                    const int bi = (nt >> 1) * 4 + (nt & 1) * 2;
                    mma_bf16(acc[mt][nt], a_h[mt], &b_h[bi]);
                    mma_bf16(acc[mt][nt], a_h[mt], &b_l[bi]);
                    mma_bf16(acc[mt][nt], a_l[mt], &b_h[bi]);
                }
        }
        if (ck + 1 < NCK) stsA(buf ^ 1);
        __syncthreads();
    }

    // ---- epilogue: bias + optional elu(x)+1, direct global stores ----
    const int r0b = bm * 128 + wr * 32 + (lane >> 2);
    const int c0b = bn * 128 + wc * 64 + (lane & 3) * 2;
#pragma unroll
    for (int mt = 0; mt < 2; mt++) {
#pragma unroll
        for (int nt = 0; nt < 8; nt++) {
            const int col = c0b + nt * 8;
            const float b0 = bias[col], b1 = bias[col + 1];
            float v[4];
            v[0] = acc[mt][nt][0] + b0;
            v[1] = acc[mt][nt][1] + b1;
            v[2] = acc[mt][nt][2] + b0;
            v[3] = acc[mt][nt][3] + b1;
            if (act) {
#pragma unroll
                for (int j = 0; j < 4; j++)
                    v[j] = (v[j] > 0.f) ? (v[j] + 1.f) : expf(v[j]);
            }
            const size_t r0 = (size_t)(r0b + mt * 16) * D + col;
            const size_t r1 = r0 + 8 * D;
            *(float2*)(C + r0) = make_float2(v[0], v[1]);
            *(float2*)(C + r1) = make_float2(v[2], v[3]);
        }
    }
}

// ---------------------------------------------------------------------------
// Stage 2: partial kv / z per (b,h) over 128-row s-chunks
// ---------------------------------------------------------------------------
__global__ __launch_bounds__(256)
void kv_partial() {
    const int bh    = blockIdx.x;
    const int chunk = blockIdx.y;
    const int b = bh >> 3, h = bh & 7;

    __shared__ float Ks[16][64];
    __shared__ float Vs[16][64];

    const int t  = threadIdx.x;
    const int m  = t & 63;
    const int dg = t >> 6;

    float acc[16];
#pragma unroll
    for (int i = 0; i < 16; i++) acc[i] = 0.f;
    float zacc = 0.f;

    const int r = t >> 4;
    const int c = (t & 15) * 4;

    for (int tile = 0; tile < 8; tile++) {
        const int s0 = chunk * 128 + tile * 16;
        const size_t base = ((size_t)(b * S + s0 + r)) * D + h * DH + c;
        *(float4*)&Ks[r][c] = *(const float4*)(g_K + base);
        *(float4*)&Vs[r][c] = *(const float4*)(g_V + base);
        __syncthreads();

#pragma unroll
        for (int rr = 0; rr < 16; rr++) {
            const float v = Vs[rr][m];
#pragma unroll
            for (int i = 0; i < 16; i++)
                acc[i] = fmaf(Ks[rr][dg * 16 + i], v, acc[i]);
        }
        if (t < 64) {
#pragma unroll
            for (int rr = 0; rr < 16; rr++) zacc += Ks[rr][t];
        }
        __syncthreads();
    }

    float* kvo = g_kvp + ((size_t)chunk * 32 + bh) * (DH * DH);
#pragma unroll
    for (int i = 0; i < 16; i++)
        kvo[(dg * 16 + i) * DH + m] = acc[i];
    if (t < 64)
        g_zp[((size_t)chunk * 32 + bh) * DH + t] = zacc;
}

__global__ __launch_bounds__(256)
void kv_reduce(float* __restrict__ out_kv, float* __restrict__ out_z) {
    const int bh = blockIdx.x;
    const int t  = threadIdx.x;
    for (int idx = t; idx < DH * DH; idx += 256) {
        float sum = 0.f;
        for (int c = 0; c < NCHUNK; c++)
            sum += g_kvp[((size_t)c * 32 + bh) * (DH * DH) + idx];
        g_kv[bh * DH * DH + idx] = sum;
        if (out_kv) out_kv[bh * DH * DH + idx] = sum;
    }
    if (t < DH) {
        float sum = 0.f;
        for (int c = 0; c < NCHUNK; c++)
            sum += g_zp[((size_t)c * 32 + bh) * DH + t];
        g_z[bh * DH + t] = sum;
        if (out_z) out_z[bh * DH + t] = sum;
    }
}

// ---------------------------------------------------------------------------
// Stage 3: recall + normalize
// ---------------------------------------------------------------------------
__global__ __launch_bounds__(256)
void attn_out() {
    const int bh = blockIdx.x;
    const int sb = blockIdx.y;
    const int b = bh >> 3, h = bh & 7;

    __shared__ float kvs[64][64];
    __shared__ float Qs[64][64];
    __shared__ float zs[64];
    __shared__ float dens[64];

    const int t = threadIdx.x;
    for (int idx = t; idx < DH * DH; idx += 256)
        kvs[idx >> 6][idx & 63] = g_kv[bh * DH * DH + idx];
    if (t < 64) zs[t] = g_z[bh * DH + t];

    const int s0 = sb * 64;
    for (int idx = t; idx < 64 * 64; idx += 256)
        Qs[idx >> 6][idx & 63] =
            g_Q[((size_t)(b * S + s0 + (idx >> 6))) * D + h * DH + (idx & 63)];
    __syncthreads();

    if (t < 64) {
        float den = 0.f;
#pragma unroll
        for (int k = 0; k < 64; k++) den = fmaf(Qs[t][k], zs[k], den);
        dens[t] = den + EPSV;
    }
    __syncthreads();

    const int m  = t & 63;
    const int rg = t >> 6;
#pragma unroll
    for (int i = 0; i < 16; i++) {
        const int r = rg * 16 + i;
        float acc = 0.f;
#pragma unroll
        for (int d = 0; d < 64; d++) acc = fmaf(Qs[r][d], kvs[d][m], acc);
        g_O[((size_t)(b * S + s0 + r)) * D + h * DH + m] = acc / dens[r];
    }
}

// ---------------------------------------------------------------------------
extern "C" void kernel_launch(void* const* d_in, const int* in_sizes, int n_in,
                              void* d_out, int out_size) {
    const float* q  = (const float*)d_in[0];
    const float* k  = (const float*)d_in[1];
    const float* v  = (const float*)d_in[2];
    const float* Wq = (const float*)d_in[3];
    const float* bq = (const float*)d_in[4];
    const float* Wk = (const float*)d_in[5];
    const float* bk = (const float*)d_in[6];
    const float* Wv = (const float*)d_in[7];
    const float* bv = (const float*)d_in[8];
    const float* Wo = (const float*)d_in[9];
    const float* bo = (const float*)d_in[10];
    float* out = (float*)d_out;

    float* gQ; cudaGetSymbolAddress((void**)&gQ, g_Q);
    float* gK; cudaGetSymbolAddress((void**)&gK, g_K);
    float* gV; cudaGetSymbolAddress((void**)&gV, g_V);
    float* gO; cudaGetSymbolAddress((void**)&gO, g_O);
    __nv_bfloat16* wh; cudaGetSymbolAddress((void**)&wh, g_Whi);
    __nv_bfloat16* wl; cudaGetSymbolAddress((void**)&wl, g_Wlo);

    cudaFuncSetAttribute(gemm_mma_f, cudaFuncAttributeMaxDynamicSharedMemorySize,
                         SMEM_SZ);

    const int NW4 = D * D / 4;
    const dim3 gg(M_TOT / 128, D / 128);

    // Q projection
    split_bf16<<<(NW4 + 255) / 256, 256>>>(Wq, wh, wl, NW4);
    gemm_mma_f<<<gg, 256, SMEM_SZ>>>(q, wh, wl, bq, gQ, 1);
    // K projection
    split_bf16<<<(NW4 + 255) / 256, 256>>>(Wk, wh, wl, NW4);
    gemm_mma_f<<<gg, 256, SMEM_SZ>>>(k, wh, wl, bk, gK, 1);
    // V projection
    split_bf16<<<(NW4 + 255) / 256, 256>>>(Wv, wh, wl, NW4);
    gemm_mma_f<<<gg, 256, SMEM_SZ>>>(v, wh, wl, bv, gV, 0);

    // kv summary + z
    kv_partial<<<dim3(B * H, NCHUNK), 256>>>();
    float* out_kv = (out_size >= Z_OFF + Z_ELEMS) ? (out + KV_OFF) : nullptr;
    float* out_z  = (out_size >= Z_OFF + Z_ELEMS) ? (out + Z_OFF)  : nullptr;
    kv_reduce<<<B * H, 256>>>(out_kv, out_z);

    // recall + normalize
    attn_out<<<dim3(B * H, S / 64), 256>>>();

    // output projection
    split_bf16<<<(NW4 + 255) / 256, 256>>>(Wo, wh, wl, NW4);
    gemm_mma_f<<<gg, 256, SMEM_SZ>>>(gO, wh, wl, bo, out, 0);
}

// round 16
// speedup vs baseline: 2.7530x; 1.1931x over previous
#include <cuda_runtime.h>
#include <cuda_bf16.h>
#include <math.h>
#include <stdint.h>

// Problem constants
#define B     4
#define S     8192
#define D     512
#define H     8
#define DH    64
#define M_TOT (B * S)          // 32768
#define EPSV  1e-6f

// Output layout: out [B,S,D] | k_v [B,H,DH,DH] | z [B,1,H,DH]
#define OUT_ELEMS  (M_TOT * D)
#define KV_ELEMS   (B * H * DH * DH)
#define Z_ELEMS    (B * H * DH)
#define KV_OFF     OUT_ELEMS
#define Z_OFF      (OUT_ELEMS + KV_ELEMS)

// ---------------- scratch (static __device__, no allocation) ----------------
__device__ __align__(256) float g_Q[M_TOT * D];
__device__ __align__(256) float g_K[M_TOT * D];
__device__ __align__(256) float g_V[M_TOT * D];
__device__ __align__(256) float g_O[M_TOT * D];

__device__ __align__(256) __nv_bfloat16 g_Whi[D * D];
__device__ __align__(256) __nv_bfloat16 g_Wlo[D * D];

#define NCHUNK 64
__device__ float g_kvp[NCHUNK * B * H * DH * DH];
__device__ float g_zp [NCHUNK * B * H * DH];
__device__ float g_kv [B * H * DH * DH];
__device__ float g_z  [B * H * DH];

// ---------------------------- PTX helpers -----------------------------------
__device__ __forceinline__ uint32_t smem_u32(const void* p) {
    uint32_t a;
    asm("{ .reg .u64 t; cvta.to.shared.u64 t, %1; cvt.u32.u64 %0, t; }"
        : "=r"(a) : "l"(p));
    return a;
}

__device__ __forceinline__ void cp_async16(uint32_t dst, const void* src) {
    asm volatile("cp.async.cg.shared.global [%0], [%1], 16;"
                 :: "r"(dst), "l"(src));
}
__device__ __forceinline__ void cp_commit() {
    asm volatile("cp.async.commit_group;");
}
template <int N>
__device__ __forceinline__ void cp_wait() {
    asm volatile("cp.async.wait_group %0;" :: "n"(N));
}

__device__ __forceinline__ void ldsm_x4(uint32_t* r, uint32_t addr) {
    asm volatile("ldmatrix.sync.aligned.m8n8.x4.shared.b16 {%0,%1,%2,%3}, [%4];"
                 : "=r"(r[0]), "=r"(r[1]), "=r"(r[2]), "=r"(r[3]) : "r"(addr));
}

__device__ __forceinline__ void mma_bf16(float* c, const uint32_t* a,
                                         const uint32_t* b) {
    asm volatile(
        "mma.sync.aligned.m16n8k16.row.col.f32.bf16.bf16.f32 "
        "{%0,%1,%2,%3}, {%4,%5,%6,%7}, {%8,%9}, {%0,%1,%2,%3};"
        : "+f"(c[0]), "+f"(c[1]), "+f"(c[2]), "+f"(c[3])
        : "r"(a[0]), "r"(a[1]), "r"(a[2]), "r"(a[3]), "r"(b[0]), "r"(b[1]));
}

__device__ __forceinline__ uint32_t pack_bf2(__nv_bfloat16 a, __nv_bfloat16 b) {
    __nv_bfloat162 t(a, b);
    return *(uint32_t*)&t;
}

// ---------------------------------------------------------------------------
// fp32 -> (bf16 hi, bf16 lo) split for the weight matrices (tiny, kept).
// ---------------------------------------------------------------------------
__global__ __launch_bounds__(256)
void split_bf16(const float* __restrict__ x, __nv_bfloat16* __restrict__ hi,
                __nv_bfloat16* __restrict__ lo, int n4) {
    int i = blockIdx.x * 256 + threadIdx.x;
    if (i >= n4) return;
    float4 v = ((const float4*)x)[i];
    __nv_bfloat16 h0 = __float2bfloat16_rn(v.x);
    __nv_bfloat16 h1 = __float2bfloat16_rn(v.y);
    __nv_bfloat16 h2 = __float2bfloat16_rn(v.z);
    __nv_bfloat16 h3 = __float2bfloat16_rn(v.w);
    __nv_bfloat16 l0 = __float2bfloat16_rn(v.x - __bfloat162float(h0));
    __nv_bfloat16 l1 = __float2bfloat16_rn(v.y - __bfloat162float(h1));
    __nv_bfloat16 l2 = __float2bfloat16_rn(v.z - __bfloat162float(h2));
    __nv_bfloat16 l3 = __float2bfloat16_rn(v.w - __bfloat162float(h3));
    __nv_bfloat162* hp = (__nv_bfloat162*)(hi + (size_t)i * 4);
    __nv_bfloat162* lp = (__nv_bfloat162*)(lo + (size_t)i * 4);
    hp[0] = __nv_bfloat162(h0, h1);
    hp[1] = __nv_bfloat162(h2, h3);
    lp[0] = __nv_bfloat162(l0, l1);
    lp[1] = __nv_bfloat162(l2, l3);
}

// ---------------------------------------------------------------------------
// HMMA GEMM with fused fp32->bf16 hi/lo split on the A (X) path. (unchanged)
// ---------------------------------------------------------------------------
#define BK     32
#define NCK    (D / BK)          // 16
#define TS     40                // smem row stride in bf16 (padded from 32)
#define TILE_B (128 * TS * 2)    // 10240 bytes per tile
#define BUF_B  (4 * TILE_B)      // Ahi, Alo, Bhi, Blo
#define SMEM_SZ (2 * BUF_B)      // 81920 bytes

__global__ __launch_bounds__(256, 2)
void gemm_mma_f(const float* __restrict__ Xf,
                const __nv_bfloat16* __restrict__ Whi,
                const __nv_bfloat16* __restrict__ Wlo,
                const float* __restrict__ bias, float* __restrict__ C, int act) {
    extern __shared__ char smem[];
    const uint32_t sb = smem_u32(smem);

    const int tid  = threadIdx.x;
    const int wid  = tid >> 5;
    const int lane = tid & 31;
    const int bm   = blockIdx.x;
    const int bn   = blockIdx.y;
    const int wr   = wid >> 1;
    const int wc   = wid & 1;

    const float* Af = Xf + (size_t)bm * 128 * D;
    const __nv_bfloat16* Bh = Whi + (size_t)bn * 128 * D;
    const __nv_bfloat16* Bl = Wlo + (size_t)bn * 128 * D;

    auto issueB = [&](int ck, int buf) {
        const int koff = ck * BK;
        const uint32_t base = sb + buf * BUF_B;
#pragma unroll
        for (int i = tid; i < 512; i += 256) {
            const int row = i >> 2, seg = i & 3;
            const uint32_t d = (uint32_t)(row * (TS * 2) + seg * 16);
            const size_t  s = (size_t)row * D + koff + seg * 8;
            cp_async16(base + 2 * TILE_B + d, Bh + s);
            cp_async16(base + 3 * TILE_B + d, Bl + s);
        }
        cp_commit();
    };

    float4 xr[4];
    auto loadX = [&](int ck) {
#pragma unroll
        for (int j = 0; j < 4; j++) {
            const int i = tid + j * 256;
            const int row = i >> 3, seg = i & 7;
            xr[j] = *(const float4*)(Af + (size_t)row * D + ck * BK + seg * 4);
        }
    };
    auto stsA = [&](int buf) {
#pragma unroll
        for (int j = 0; j < 4; j++) {
            const int i = tid + j * 256;
            const int row = i >> 3, seg = i & 7;
            const float4 v = xr[j];
            const __nv_bfloat16 h0 = __float2bfloat16_rn(v.x);
            const __nv_bfloat16 h1 = __float2bfloat16_rn(v.y);
            const __nv_bfloat16 h2 = __float2bfloat16_rn(v.z);
            const __nv_bfloat16 h3 = __float2bfloat16_rn(v.w);
            const __nv_bfloat16 l0 = __float2bfloat16_rn(v.x - __bfloat162float(h0));
            const __nv_bfloat16 l1 = __float2bfloat16_rn(v.y - __bfloat162float(h1));
            const __nv_bfloat16 l2 = __float2bfloat16_rn(v.z - __bfloat162float(h2));
            const __nv_bfloat16 l3 = __float2bfloat16_rn(v.w - __bfloat162float(h3));
            const uint32_t off = (uint32_t)(row * TS + seg * 4) * 2;
            *(uint2*)(smem + buf * BUF_B + 0 * TILE_B + off) =
                make_uint2(pack_bf2(h0, h1), pack_bf2(h2, h3));
            *(uint2*)(smem + buf * BUF_B + 1 * TILE_B + off) =
                make_uint2(pack_bf2(l0, l1), pack_bf2(l2, l3));
        }
    };

    float acc[2][8][4];
#pragma unroll
    for (int m = 0; m < 2; m++)
#pragma unroll
        for (int n = 0; n < 8; n++)
#pragma unroll
            for (int j = 0; j < 4; j++) acc[m][n][j] = 0.f;

    loadX(0);
    issueB(0, 0);
    stsA(0);

    for (int ck = 0; ck < NCK; ck++) {
        const int buf = ck & 1;
        if (ck + 1 < NCK) { loadX(ck + 1); issueB(ck + 1, buf ^ 1); cp_wait<1>(); }
        else              { cp_wait<0>(); }
        __syncthreads();

        const uint32_t ahi = sb + buf * BUF_B + 0 * TILE_B;
        const uint32_t alo = sb + buf * BUF_B + 1 * TILE_B;
        const uint32_t bhi = sb + buf * BUF_B + 2 * TILE_B;
        const uint32_t blo = sb + buf * BUF_B + 3 * TILE_B;

#pragma unroll
        for (int ks = 0; ks < 2; ks++) {
            const int ar = lane & 15, ac = (lane >> 4) * 8;
            uint32_t a_h[2][4], a_l[2][4];
#pragma unroll
            for (int mt = 0; mt < 2; mt++) {
                const uint32_t off =
                    (uint32_t)((wr * 32 + mt * 16 + ar) * TS + ks * 16 + ac) * 2;
                ldsm_x4(a_h[mt], ahi + off);
                ldsm_x4(a_l[mt], alo + off);
            }
            const int bp = lane & 7, bk8 = ((lane >> 3) & 1) * 8,
                      bn8 = ((lane >> 4) & 1) * 8;
            uint32_t b_h[16], b_l[16];
#pragma unroll
            for (int nt4 = 0; nt4 < 4; nt4++) {
                const int nrow = wc * 64 + nt4 * 16 + bp + bn8;
                const uint32_t off = (uint32_t)(nrow * TS + ks * 16 + bk8) * 2;
                ldsm_x4(&b_h[nt4 * 4], bhi + off);
                ldsm_x4(&b_l[nt4 * 4], blo + off);
            }
#pragma unroll
            for (int mt = 0; mt < 2; mt++)
#pragma unroll
                for (int nt = 0; nt < 8; nt++) {
                    const int bi = (nt >> 1) * 4 + (nt & 1) * 2;
                    mma_bf16(acc[mt][nt], a_h[mt], &b_h[bi]);
                    mma_bf16(acc[mt][nt], a_h[mt], &b_l[bi]);
                    mma_bf16(acc[mt][nt], a_l[mt], &b_h[bi]);
                }
        }
        if (ck + 1 < NCK) stsA(buf ^ 1);
        __syncthreads();
    }

    const int r0b = bm * 128 + wr * 32 + (lane >> 2);
    const int c0b = bn * 128 + wc * 64 + (lane & 3) * 2;
#pragma unroll
    for (int mt = 0; mt < 2; mt++) {
#pragma unroll
        for (int nt = 0; nt < 8; nt++) {
            const int col = c0b + nt * 8;
            const float b0 = bias[col], b1 = bias[col + 1];
            float v[4];
            v[0] = acc[mt][nt][0] + b0;
            v[1] = acc[mt][nt][1] + b1;
            v[2] = acc[mt][nt][2] + b0;
            v[3] = acc[mt][nt][3] + b1;
            if (act) {
#pragma unroll
                for (int j = 0; j < 4; j++)
                    v[j] = (v[j] > 0.f) ? (v[j] + 1.f) : expf(v[j]);
            }
            const size_t r0 = (size_t)(r0b + mt * 16) * D + col;
            const size_t r1 = r0 + 8 * D;
            *(float2*)(C + r0) = make_float2(v[0], v[1]);
            *(float2*)(C + r1) = make_float2(v[2], v[3]);
        }
    }
}

// ---------------------------------------------------------------------------
// Stage 2: partial kv / z per (b,h) over 128-row s-chunks (float4 K loads)
// ---------------------------------------------------------------------------
__global__ __launch_bounds__(256)
void kv_partial() {
    const int bh    = blockIdx.x;
    const int chunk = blockIdx.y;
    const int b = bh >> 3, h = bh & 7;

    __shared__ float Ks[16][64];
    __shared__ float Vs[16][64];

    const int t  = threadIdx.x;
    const int m  = t & 63;
    const int dg = t >> 6;

    float acc[16];
#pragma unroll
    for (int i = 0; i < 16; i++) acc[i] = 0.f;
    float zacc = 0.f;

    const int r = t >> 4;
    const int c = (t & 15) * 4;

    for (int tile = 0; tile < 8; tile++) {
        const int s0 = chunk * 128 + tile * 16;
        const size_t base = ((size_t)(b * S + s0 + r)) * D + h * DH + c;
        *(float4*)&Ks[r][c] = *(const float4*)(g_K + base);
        *(float4*)&Vs[r][c] = *(const float4*)(g_V + base);
        __syncthreads();

#pragma unroll
        for (int rr = 0; rr < 16; rr++) {
            const float v = Vs[rr][m];
            const float4 k0 = *(const float4*)&Ks[rr][dg * 16 + 0];
            const float4 k1 = *(const float4*)&Ks[rr][dg * 16 + 4];
            const float4 k2 = *(const float4*)&Ks[rr][dg * 16 + 8];
            const float4 k3 = *(const float4*)&Ks[rr][dg * 16 + 12];
            acc[0]  = fmaf(k0.x, v, acc[0]);
            acc[1]  = fmaf(k0.y, v, acc[1]);
            acc[2]  = fmaf(k0.z, v, acc[2]);
            acc[3]  = fmaf(k0.w, v, acc[3]);
            acc[4]  = fmaf(k1.x, v, acc[4]);
            acc[5]  = fmaf(k1.y, v, acc[5]);
            acc[6]  = fmaf(k1.z, v, acc[6]);
            acc[7]  = fmaf(k1.w, v, acc[7]);
            acc[8]  = fmaf(k2.x, v, acc[8]);
            acc[9]  = fmaf(k2.y, v, acc[9]);
            acc[10] = fmaf(k2.z, v, acc[10]);
            acc[11] = fmaf(k2.w, v, acc[11]);
            acc[12] = fmaf(k3.x, v, acc[12]);
            acc[13] = fmaf(k3.y, v, acc[13]);
            acc[14] = fmaf(k3.z, v, acc[14]);
            acc[15] = fmaf(k3.w, v, acc[15]);
        }
        if (t < 64) {
#pragma unroll
            for (int rr = 0; rr < 16; rr++) zacc += Ks[rr][t];
        }
        __syncthreads();
    }

    float* kvo = g_kvp + ((size_t)chunk * 32 + bh) * (DH * DH);
#pragma unroll
    for (int i = 0; i < 16; i++)
        kvo[(dg * 16 + i) * DH + m] = acc[i];
    if (t < 64)
        g_zp[((size_t)chunk * 32 + bh) * DH + t] = zacc;
}

// Reduce partials — fully parallel: 512 blocks, one output element per thread.
__global__ __launch_bounds__(256)
void kv_reduce(float* __restrict__ out_kv, float* __restrict__ out_z) {
    const int bid = blockIdx.x;            // 512 blocks
    const int bh  = bid >> 4;              // 32 bh, 16 blocks each
    const int idx = (bid & 15) * 256 + threadIdx.x;   // 0..4095

    float sum = 0.f;
#pragma unroll 4
    for (int c = 0; c < NCHUNK; c++)
        sum += g_kvp[((size_t)c * 32 + bh) * (DH * DH) + idx];
    g_kv[bh * DH * DH + idx] = sum;
    if (out_kv) out_kv[bh * DH * DH + idx] = sum;

    // z: blocks with (bid & 15) == 0 reduce the 64 z values for their bh
    if ((bid & 15) == 0 && threadIdx.x < DH) {
        const int d = threadIdx.x;
        float zs = 0.f;
#pragma unroll 4
        for (int c = 0; c < NCHUNK; c++)
            zs += g_zp[((size_t)c * 32 + bh) * DH + d];
        g_z[bh * DH + d] = zs;
        if (out_z) out_z[bh * DH + d] = zs;
    }
}

// ---------------------------------------------------------------------------
// Stage 3: recall + normalize — 4x4 register blocking per thread
// ---------------------------------------------------------------------------
__global__ __launch_bounds__(256)
void attn_out() {
    const int bh = blockIdx.x;
    const int sb = blockIdx.y;
    const int b = bh >> 3, h = bh & 7;

    __shared__ float kvs[64][64];
    __shared__ float Qs[64][65];       // padded: row-varying broadcast reads
    __shared__ float zs[64];
    __shared__ float dens[64];

    const int t = threadIdx.x;
    for (int idx = t; idx < DH * DH; idx += 256)
        kvs[idx >> 6][idx & 63] = g_kv[bh * DH * DH + idx];
    if (t < 64) zs[t] = g_z[bh * DH + t];

    const int s0 = sb * 64;
    for (int idx = t; idx < 64 * 64; idx += 256)
        Qs[idx >> 6][idx & 63] =
            g_Q[((size_t)(b * S + s0 + (idx >> 6))) * D + h * DH + (idx & 63)];
    __syncthreads();

    if (t < 64) {
        float den = 0.f;
#pragma unroll
        for (int k = 0; k < 64; k++) den = fmaf(Qs[t][k], zs[k], den);
        dens[t] = den + EPSV;
    }
    __syncthreads();

    const int tr = t >> 4;             // row group 0..15 (4 rows each)
    const int tc = t & 15;             // col group 0..15 (4 cols each)

    float acc[4][4];
#pragma unroll
    for (int i = 0; i < 4; i++)
#pragma unroll
        for (int j = 0; j < 4; j++) acc[i][j] = 0.f;

#pragma unroll 4
    for (int d = 0; d < 64; d++) {
        const float4 kv4 = *(const float4*)&kvs[d][tc * 4];
#pragma unroll
        for (int i = 0; i < 4; i++) {
            const float qv = Qs[tr * 4 + i][d];
            acc[i][0] = fmaf(qv, kv4.x, acc[i][0]);
            acc[i][1] = fmaf(qv, kv4.y, acc[i][1]);
            acc[i][2] = fmaf(qv, kv4.z, acc[i][2]);
            acc[i][3] = fmaf(qv, kv4.w, acc[i][3]);
        }
    }

#pragma unroll
    for (int i = 0; i < 4; i++) {
        const int r = tr * 4 + i;
        const float inv = 1.f / dens[r];
        float4 o = make_float4(acc[i][0] * inv, acc[i][1] * inv,
                               acc[i][2] * inv, acc[i][3] * inv);
        *(float4*)(g_O + ((size_t)(b * S + s0 + r)) * D + h * DH + tc * 4) = o;
    }
}

// ---------------------------------------------------------------------------
extern "C" void kernel_launch(void* const* d_in, const int* in_sizes, int n_in,
                              void* d_out, int out_size) {
    const float* q  = (const float*)d_in[0];
    const float* k  = (const float*)d_in[1];
    const float* v  = (const float*)d_in[2];
    const float* Wq = (const float*)d_in[3];
    const float* bq = (const float*)d_in[4];
    const float* Wk = (const float*)d_in[5];
    const float* bk = (const float*)d_in[6];
    const float* Wv = (const float*)d_in[7];
    const float* bv = (const float*)d_in[8];
    const float* Wo = (const float*)d_in[9];
    const float* bo = (const float*)d_in[10];
    float* out = (float*)d_out;

    float* gQ; cudaGetSymbolAddress((void**)&gQ, g_Q);
    float* gK; cudaGetSymbolAddress((void**)&gK, g_K);
    float* gV; cudaGetSymbolAddress((void**)&gV, g_V);
    float* gO; cudaGetSymbolAddress((void**)&gO, g_O);
    __nv_bfloat16* wh; cudaGetSymbolAddress((void**)&wh, g_Whi);
    __nv_bfloat16* wl; cudaGetSymbolAddress((void**)&wl, g_Wlo);

    cudaFuncSetAttribute(gemm_mma_f, cudaFuncAttributeMaxDynamicSharedMemorySize,
                         SMEM_SZ);

    const int NW4 = D * D / 4;
    const dim3 gg(M_TOT / 128, D / 128);

    // Q projection
    split_bf16<<<(NW4 + 255) / 256, 256>>>(Wq, wh, wl, NW4);
    gemm_mma_f<<<gg, 256, SMEM_SZ>>>(q, wh, wl, bq, gQ, 1);
    // K projection
    split_bf16<<<(NW4 + 255) / 256, 256>>>(Wk, wh, wl, NW4);
    gemm_mma_f<<<gg, 256, SMEM_SZ>>>(k, wh, wl, bk, gK, 1);
    // V projection
    split_bf16<<<(NW4 + 255) / 256, 256>>>(Wv, wh, wl, NW4);
    gemm_mma_f<<<gg, 256, SMEM_SZ>>>(v, wh, wl, bv, gV, 0);

    // kv summary + z
    kv_partial<<<dim3(B * H, NCHUNK), 256>>>();
    float* out_kv = (out_size >= Z_OFF + Z_ELEMS) ? (out + KV_OFF) : nullptr;
    float* out_z  = (out_size >= Z_OFF + Z_ELEMS) ? (out + Z_OFF)  : nullptr;
    kv_reduce<<<512, 256>>>(out_kv, out_z);

    // recall + normalize
    attn_out<<<dim3(B * H, S / 64), 256>>>();

    // output projection
    split_bf16<<<(NW4 + 255) / 256, 256>>>(Wo, wh, wl, NW4);
    gemm_mma_f<<<gg, 256, SMEM_SZ>>>(gO, wh, wl, bo, out, 0);
}